// round 6
// baseline (speedup 1.0000x reference)
#include <cuda_runtime.h>

#define NSEQ 1024
#define CH   64
#define NPTS (2 * NSEQ)

// Scratch (allocation-free rule: __device__ globals)
__device__ float g_Ui [NPTS * CH];  //  y + b1   (i side)
__device__ float g_Ujn[NPTS * CH];  // -y        (j side, pre-negated)
__device__ float g_rI [NPTS];       //  sum_c w2h*(y+b1) + b2
__device__ float g_rJn[NPTS];       //  sum_c w2h*(-y)

// ---------------------------------------------------------------------------
// K1: y[p][o] = sum_c W1[o][c] * x[p][c];  Ui = y+b1; Ujn = -y
//     plus per-point scalars rI, rJn via warp reduction.
// 128 blocks x 16 points, 256 threads (o = t&63, pg = t>>6).
// ---------------------------------------------------------------------------
__global__ void k1_proj(const float* __restrict__ x,
                        const float* __restrict__ w1,
                        const float* __restrict__ b1,
                        const float* __restrict__ w2,
                        const float* __restrict__ b2p) {
    __shared__ float W1T[CH][65];                  // [c][o]
    __shared__ __align__(16) float xsT[CH][20];    // [c][p]
    __shared__ float b1s[CH];
    __shared__ float w2s[CH];
    __shared__ float part[4][2][8];

    int t = threadIdx.x;
    int p0 = blockIdx.x * 16;

#pragma unroll
    for (int q = t; q < 1024; q += 256) {
        int o = q >> 4, c4 = (q & 15) * 4;
        float4 v = reinterpret_cast<const float4*>(w1)[q];
        W1T[c4 + 0][o] = v.x;
        W1T[c4 + 1][o] = v.y;
        W1T[c4 + 2][o] = v.z;
        W1T[c4 + 3][o] = v.w;
    }
    {
        int pl = t >> 4, c4 = (t & 15) * 4;
        float4 v = reinterpret_cast<const float4*>(x + p0 * CH)[t];
        xsT[c4 + 0][pl] = v.x;
        xsT[c4 + 1][pl] = v.y;
        xsT[c4 + 2][pl] = v.z;
        xsT[c4 + 3][pl] = v.w;
    }
    if (t < CH) { b1s[t] = b1[t]; w2s[t] = 0.5f * w2[t]; }
    __syncthreads();

    int o = t & 63, pg = t >> 6;
    float a0 = 0.f, a1 = 0.f, a2 = 0.f, a3 = 0.f;
#pragma unroll
    for (int c = 0; c < CH; ++c) {
        float wv = W1T[c][o];
        float4 xv = *reinterpret_cast<const float4*>(&xsT[c][pg * 4]);
        a0 += wv * xv.x;
        a1 += wv * xv.y;
        a2 += wv * xv.z;
        a3 += wv * xv.w;
    }

    float b1v = b1s[o];
    int pbase = p0 + pg * 4;
    g_Ujn[(pbase + 0) * CH + o] = -a0;  g_Ui[(pbase + 0) * CH + o] = a0 + b1v;
    g_Ujn[(pbase + 1) * CH + o] = -a1;  g_Ui[(pbase + 1) * CH + o] = a1 + b1v;
    g_Ujn[(pbase + 2) * CH + o] = -a2;  g_Ui[(pbase + 2) * CH + o] = a2 + b1v;
    g_Ujn[(pbase + 3) * CH + o] = -a3;  g_Ui[(pbase + 3) * CH + o] = a3 + b1v;

    // Per-point scalars: reduce over o (2 warps per pg)
    float w2ho = w2s[o];
    float ci0 = w2ho * (a0 + b1v), cj0 = -w2ho * a0;
    float ci1 = w2ho * (a1 + b1v), cj1 = -w2ho * a1;
    float ci2 = w2ho * (a2 + b1v), cj2 = -w2ho * a2;
    float ci3 = w2ho * (a3 + b1v), cj3 = -w2ho * a3;
#pragma unroll
    for (int off = 16; off; off >>= 1) {
        ci0 += __shfl_xor_sync(0xffffffffu, ci0, off);
        ci1 += __shfl_xor_sync(0xffffffffu, ci1, off);
        ci2 += __shfl_xor_sync(0xffffffffu, ci2, off);
        ci3 += __shfl_xor_sync(0xffffffffu, ci3, off);
        cj0 += __shfl_xor_sync(0xffffffffu, cj0, off);
        cj1 += __shfl_xor_sync(0xffffffffu, cj1, off);
        cj2 += __shfl_xor_sync(0xffffffffu, cj2, off);
        cj3 += __shfl_xor_sync(0xffffffffu, cj3, off);
    }
    if ((t & 31) == 0) {
        int h = (t >> 5) & 1;
        part[pg][h][0] = ci0;  part[pg][h][1] = ci1;
        part[pg][h][2] = ci2;  part[pg][h][3] = ci3;
        part[pg][h][4] = cj0;  part[pg][h][5] = cj1;
        part[pg][h][6] = cj2;  part[pg][h][7] = cj3;
    }
    __syncthreads();
    if (t < 32) {
        int pgx = t >> 3, idx = t & 7;
        float v = part[pgx][0][idx] + part[pgx][1][idx];
        int p = p0 + pgx * 4 + (idx & 3);
        if (idx < 4) g_rI[p] = v + b2p[0];
        else         g_rJn[p] = v;
    }
}

// ---------------------------------------------------------------------------
// K2 fused: scores + row softmax, one output write.
// Block: 4 i-rows x all 1024 j. Grid (256, 2) = 512 blocks, 256 threads.
// Thread: tx = t&127 (j within chunk), ty2 = t>>7 (2 i-rows each).
// j streamed in 8 chunks of 128 rows via smem. Scores in 16 regs/thread.
// ---------------------------------------------------------------------------
__global__ void __launch_bounds__(256)
k2_fused(const float* __restrict__ w2, float* __restrict__ out) {
    __shared__ __align__(16) float Uis[4][68];
    __shared__ __align__(16) float Ujs[128][68];
    __shared__ __align__(16) float w2hs[CH];
    __shared__ float rIs[4];
    __shared__ __align__(16) float rJc[128];
    __shared__ float rmax[8][2];
    __shared__ float rsum[8][2];

    int t  = threadIdx.x;
    int tx = t & 127, ty2 = t >> 7;
    int it = blockIdx.x, b = blockIdx.y;

    const float* UiG = g_Ui + (size_t)(b * NSEQ + it * 4) * CH;
    if (t < 64) {  // 4 rows x 16 float4
        float4 v = reinterpret_cast<const float4*>(UiG)[t];
        *reinterpret_cast<float4*>(&Uis[t >> 4][(t & 15) * 4]) = v;
    } else if (t < 128) {
        w2hs[t - 64] = 0.5f * w2[t - 64];
    } else if (t < 132) {
        rIs[t - 128] = g_rI[b * NSEQ + it * 4 + (t - 128)];
    }

    float s[16];

#pragma unroll 1
    for (int cc = 0; cc < 8; ++cc) {
        __syncthreads();  // protect Ujs/rJc before restaging (and Uis on cc=0)
        const float* UjG = g_Ujn + (size_t)(b * NSEQ + cc * 128) * CH;
#pragma unroll
        for (int q8 = 0; q8 < 8; ++q8) {
            int q = q8 * 256 + t;
            int row = q >> 4, c4 = (q & 15) * 4;
            float4 v = reinterpret_cast<const float4*>(UjG)[q];
            *reinterpret_cast<float4*>(&Ujs[row][c4]) = v;
        }
        if (t < 32) {
            float4 v = reinterpret_cast<const float4*>(g_rJn + b * NSEQ + cc * 128)[t];
            *reinterpret_cast<float4*>(&rJc[t * 4]) = v;
        }
        __syncthreads();

        float a0 = 0.f, a1 = 0.f;
#pragma unroll
        for (int c = 0; c < CH; c += 4) {
            float4 w4 = *reinterpret_cast<const float4*>(&w2hs[c]);
            float4 y0 = *reinterpret_cast<const float4*>(&Uis[2 * ty2][c]);
            float4 y1 = *reinterpret_cast<const float4*>(&Uis[2 * ty2 + 1][c]);
            float4 z  = *reinterpret_cast<const float4*>(&Ujs[tx][c]);
            a0 += w4.x * fabsf(y0.x + z.x);
            a0 += w4.y * fabsf(y0.y + z.y);
            a0 += w4.z * fabsf(y0.z + z.z);
            a0 += w4.w * fabsf(y0.w + z.w);
            a1 += w4.x * fabsf(y1.x + z.x);
            a1 += w4.y * fabsf(y1.y + z.y);
            a1 += w4.z * fabsf(y1.z + z.z);
            a1 += w4.w * fabsf(y1.w + z.w);
        }
        float rj = rJc[tx];
        s[2 * cc]     = rIs[2 * ty2]     + rj + a0;
        s[2 * cc + 1] = rIs[2 * ty2 + 1] + rj + a1;
    }

    // ---- row softmax (rows 2*ty2 and 2*ty2+1) ----
    float m0 = s[0], m1 = s[1];
#pragma unroll
    for (int cc = 1; cc < 8; ++cc) {
        m0 = fmaxf(m0, s[2 * cc]);
        m1 = fmaxf(m1, s[2 * cc + 1]);
    }
#pragma unroll
    for (int off = 16; off; off >>= 1) {
        m0 = fmaxf(m0, __shfl_xor_sync(0xffffffffu, m0, off));
        m1 = fmaxf(m1, __shfl_xor_sync(0xffffffffu, m1, off));
    }
    int w = t >> 5;
    if ((t & 31) == 0) { rmax[w][0] = m0; rmax[w][1] = m1; }
    __syncthreads();
    int wbase = ty2 * 4;
    float M0 = fmaxf(fmaxf(rmax[wbase][0], rmax[wbase + 1][0]),
                     fmaxf(rmax[wbase + 2][0], rmax[wbase + 3][0]));
    float M1 = fmaxf(fmaxf(rmax[wbase][1], rmax[wbase + 1][1]),
                     fmaxf(rmax[wbase + 2][1], rmax[wbase + 3][1]));

    float t0 = 0.f, t1 = 0.f;
#pragma unroll
    for (int cc = 0; cc < 8; ++cc) {
        float e0 = __expf(s[2 * cc] - M0);
        float e1 = __expf(s[2 * cc + 1] - M1);
        s[2 * cc] = e0;  s[2 * cc + 1] = e1;
        t0 += e0;  t1 += e1;
    }
#pragma unroll
    for (int off = 16; off; off >>= 1) {
        t0 += __shfl_xor_sync(0xffffffffu, t0, off);
        t1 += __shfl_xor_sync(0xffffffffu, t1, off);
    }
    if ((t & 31) == 0) { rsum[w][0] = t0; rsum[w][1] = t1; }
    __syncthreads();
    float S0 = (rsum[wbase][0] + rsum[wbase + 1][0]) +
               (rsum[wbase + 2][0] + rsum[wbase + 3][0]);
    float S1 = (rsum[wbase][1] + rsum[wbase + 1][1]) +
               (rsum[wbase + 2][1] + rsum[wbase + 3][1]);
    float inv0 = 1.0f / S0, inv1 = 1.0f / S1;

    size_t row0 = ((size_t)b * NSEQ + it * 4 + 2 * ty2) * NSEQ;
#pragma unroll
    for (int cc = 0; cc < 8; ++cc) {
        out[row0 + cc * 128 + tx]        = s[2 * cc] * inv0;
        out[row0 + NSEQ + cc * 128 + tx] = s[2 * cc + 1] * inv1;
    }
}

// ---------------------------------------------------------------------------
extern "C" void kernel_launch(void* const* d_in, const int* in_sizes, int n_in,
                              void* d_out, int out_size) {
    const float* x  = (const float*)d_in[0];  // [2,1024,64]
    const float* w1 = (const float*)d_in[1];  // [64,64]
    const float* b1 = (const float*)d_in[2];  // [64]
    const float* w2 = (const float*)d_in[3];  // [64]
    const float* b2 = (const float*)d_in[4];  // scalar
    float* out = (float*)d_out;               // [2,1024,1024]

    k1_proj<<<128, 256>>>(x, w1, b1, w2, b2);
    dim3 g2(256, 2);
    k2_fused<<<g2, 256>>>(w2, out);
}

// round 7
// speedup vs baseline: 1.5714x; 1.5714x over previous
#include <cuda_runtime.h>

#define NSEQ 1024
#define CH   64
#define NPTS (2 * NSEQ)

// Scratch (allocation-free rule: __device__ globals)
__device__ float g_Ui [NPTS * CH];  //  y + b1   (i side)
__device__ float g_Ujn[NPTS * CH];  // -y        (j side, pre-negated)
__device__ float g_rI [NPTS];       //  sum_c w2h*(y+b1) + b2
__device__ float g_rJn[NPTS];       //  sum_c w2h*(-y)

// ---------------------------------------------------------------------------
// K1: y[p][o] = sum_c W1[o][c] * x[p][c];  Ui = y+b1; Ujn = -y
//     plus per-point scalars rI, rJn via warp reduction.
// 512 blocks x 4 points, 256 threads (o = t&63, pl = t>>6; one output/thread).
// ---------------------------------------------------------------------------
__global__ void k1_proj(const float* __restrict__ x,
                        const float* __restrict__ w1,
                        const float* __restrict__ b1,
                        const float* __restrict__ w2,
                        const float* __restrict__ b2p) {
    __shared__ __align__(16) float W1s[CH][68];   // [o][c] straight, padded
    __shared__ __align__(16) float xs[4][CH];
    __shared__ float b1s[CH];
    __shared__ float w2s[CH];
    __shared__ float part[4][2][2];               // [pl][half][{i,j}]

    int t = threadIdx.x;
    int p0 = blockIdx.x * 4;

    // Stage W1 rows straight: 1024 float4s, 4 per thread
#pragma unroll
    for (int q = t; q < 1024; q += 256) {
        float4 v = reinterpret_cast<const float4*>(w1)[q];
        *reinterpret_cast<float4*>(&W1s[q >> 4][(q & 15) * 4]) = v;
    }
    if (t < 64) {
        b1s[t] = b1[t];
        w2s[t] = 0.5f * w2[t];
        // 4 points x 64 ch = 64 float4
        float4 v = reinterpret_cast<const float4*>(x + p0 * CH)[t];
        *reinterpret_cast<float4*>(&xs[t >> 4][(t & 15) * 4]) = v;
    }
    __syncthreads();

    int o = t & 63, pl = t >> 6;
    float acc = 0.f;
#pragma unroll
    for (int c = 0; c < CH; c += 4) {
        float4 wv = *reinterpret_cast<const float4*>(&W1s[o][c]);
        float4 xv = *reinterpret_cast<const float4*>(&xs[pl][c]);
        acc += wv.x * xv.x;
        acc += wv.y * xv.y;
        acc += wv.z * xv.z;
        acc += wv.w * xv.w;
    }

    float ui = acc + b1s[o];
    int g = (p0 + pl) * CH + o;
    g_Ujn[g] = -acc;
    g_Ui [g] = ui;

    // Per-point scalars: each point spans exactly 2 warps (o split 0-31/32-63)
    float w2ho = w2s[o];
    float ci = w2ho * ui;
    float cj = -w2ho * acc;
#pragma unroll
    for (int off = 16; off; off >>= 1) {
        ci += __shfl_xor_sync(0xffffffffu, ci, off);
        cj += __shfl_xor_sync(0xffffffffu, cj, off);
    }
    if ((t & 31) == 0) {
        int h = (t >> 5) & 1;
        part[pl][h][0] = ci;
        part[pl][h][1] = cj;
    }
    __syncthreads();
    if (t < 8) {
        int plx = t >> 1, which = t & 1;
        float v = part[plx][0][which] + part[plx][1][which];
        int p = p0 + plx;
        if (which == 0) g_rI[p]  = v + b2p[0];
        else            g_rJn[p] = v;
    }
}

// ---------------------------------------------------------------------------
// K2: raw scores. score[i,j] = rI_i + rJn_j + sum_c w2h[c]*|Ui[i][c]+Ujn[j][c]|
// Block tile 64x64, 256 threads, 4x4 microtile (proven compute-bound shape).
// Grid: (jt=16, it=16, b=2)
// ---------------------------------------------------------------------------
__global__ void k2_scores(const float* __restrict__ w2,
                          float* __restrict__ out) {
    __shared__ __align__(16) float Uis[64][68];
    __shared__ __align__(16) float Ujs[64][68];
    __shared__ float w2hs[CH];
    __shared__ float rIs[64], rJn[64];

    int t  = threadIdx.x;
    int jt = blockIdx.x, it = blockIdx.y, b = blockIdx.z;

    const float* Ui = g_Ui  + ((b * NSEQ + it * 64) * CH);
    const float* Uj = g_Ujn + ((b * NSEQ + jt * 64) * CH);

#pragma unroll
    for (int iter = 0; iter < 4; ++iter) {
        int q   = iter * 256 + t;
        int row = q >> 4, cq = (q & 15) * 4;
        float4 v = reinterpret_cast<const float4*>(Ui)[q];
        *reinterpret_cast<float4*>(&Uis[row][cq]) = v;
        float4 u = reinterpret_cast<const float4*>(Uj)[q];
        *reinterpret_cast<float4*>(&Ujs[row][cq]) = u;
    }
    if (t < CH) {
        w2hs[t] = 0.5f * w2[t];
        rIs[t] = g_rI[b * NSEQ + it * 64 + t];
    } else if (t < 128) {
        rJn[t - 64] = g_rJn[b * NSEQ + jt * 64 + (t - 64)];
    }
    __syncthreads();

    int tx = t & 15, ty = t >> 4;   // i_local = ty + 16r, j_local = tx + 16s
    float acc[4][4] = {};

#pragma unroll
    for (int c = 0; c < CH; c += 4) {
        float4 w4 = *reinterpret_cast<const float4*>(&w2hs[c]);
        float4 yi[4], yj[4];
#pragma unroll
        for (int r = 0; r < 4; ++r)
            yi[r] = *reinterpret_cast<const float4*>(&Uis[ty + 16 * r][c]);
#pragma unroll
        for (int s = 0; s < 4; ++s)
            yj[s] = *reinterpret_cast<const float4*>(&Ujs[tx + 16 * s][c]);
#pragma unroll
        for (int r = 0; r < 4; ++r)
#pragma unroll
            for (int s = 0; s < 4; ++s) {
                acc[r][s] += w4.x * fabsf(yi[r].x + yj[s].x);
                acc[r][s] += w4.y * fabsf(yi[r].y + yj[s].y);
                acc[r][s] += w4.z * fabsf(yi[r].z + yj[s].z);
                acc[r][s] += w4.w * fabsf(yi[r].w + yj[s].w);
            }
    }

#pragma unroll
    for (int r = 0; r < 4; ++r) {
        int ig   = it * 64 + ty + 16 * r;
        float ri = rIs[ty + 16 * r];
        float* orow = out + (size_t)(b * NSEQ + ig) * NSEQ + jt * 64;
#pragma unroll
        for (int s = 0; s < 4; ++s) {
            orow[tx + 16 * s] = ri + rJn[tx + 16 * s] + acc[r][s];
        }
    }
}

// ---------------------------------------------------------------------------
// K3: in-place row softmax over j. One block per (b,i) row. 256 threads,
// float4 vectorized (1 LDG.128 + 1 STG.128 per thread).
// ---------------------------------------------------------------------------
__global__ void k3_softmax(float* __restrict__ out) {
    __shared__ float red[8];
    __shared__ float bcast;
    size_t base = (size_t)blockIdx.x * NSEQ;
    int t = threadIdx.x;

    float4 v = reinterpret_cast<const float4*>(out + base)[t];

    float m = fmaxf(fmaxf(v.x, v.y), fmaxf(v.z, v.w));
#pragma unroll
    for (int o = 16; o; o >>= 1) m = fmaxf(m, __shfl_xor_sync(0xffffffffu, m, o));
    if ((t & 31) == 0) red[t >> 5] = m;
    __syncthreads();
    if (t == 0) {
        float mm = red[0];
#pragma unroll
        for (int i = 1; i < 8; ++i) mm = fmaxf(mm, red[i]);
        bcast = mm;
    }
    __syncthreads();
    m = bcast;

    float4 e;
    e.x = __expf(v.x - m);
    e.y = __expf(v.y - m);
    e.z = __expf(v.z - m);
    e.w = __expf(v.w - m);
    float s = (e.x + e.y) + (e.z + e.w);
#pragma unroll
    for (int o = 16; o; o >>= 1) s += __shfl_xor_sync(0xffffffffu, s, o);
    __syncthreads();
    if ((t & 31) == 0) red[t >> 5] = s;
    __syncthreads();
    if (t == 0) {
        float ss = red[0];
#pragma unroll
        for (int i = 1; i < 8; ++i) ss += red[i];
        bcast = 1.0f / ss;
    }
    __syncthreads();
    float inv = bcast;

    e.x *= inv;  e.y *= inv;  e.z *= inv;  e.w *= inv;
    reinterpret_cast<float4*>(out + base)[t] = e;
}

// ---------------------------------------------------------------------------
extern "C" void kernel_launch(void* const* d_in, const int* in_sizes, int n_in,
                              void* d_out, int out_size) {
    const float* x  = (const float*)d_in[0];  // [2,1024,64]
    const float* w1 = (const float*)d_in[1];  // [64,64]
    const float* b1 = (const float*)d_in[2];  // [64]
    const float* w2 = (const float*)d_in[3];  // [64]
    const float* b2 = (const float*)d_in[4];  // scalar
    float* out = (float*)d_out;               // [2,1024,1024]

    k1_proj<<<512, 256>>>(x, w1, b1, w2, b2);
    dim3 g2(16, 16, 2);
    k2_scores<<<g2, 256>>>(w2, out);
    k3_softmax<<<2048, 256>>>(out);
}

// round 8
// speedup vs baseline: 1.6903x; 1.0756x over previous
#include <cuda_runtime.h>

#define NSEQ 1024
#define CH   64
#define NPTS (2 * NSEQ)

// Scratch (allocation-free rule: __device__ globals)
__device__ float g_Yi[NPTS * CH];   // y + b1   (i side)
__device__ float g_Yj[NPTS * CH];   // -y       (j side, pre-negated)

// ---------------------------------------------------------------------------
// K1: y[p][o] = sum_c W1[o][c] * x[p][c];  Yi = y + b1; Yj = -y
// 128 blocks x 16 points, 256 threads. Thread: o = t&63, point-group pg = t>>6
// (4 points each). W1 staged transposed [c][o], x transposed [c][p].
// (Exact R3 configuration — best measured k1.)
// ---------------------------------------------------------------------------
__global__ void k1_proj(const float* __restrict__ x,
                        const float* __restrict__ w1,
                        const float* __restrict__ b1) {
    __shared__ float W1T[CH][65];                  // [c][o]
    __shared__ __align__(16) float xsT[CH][20];    // [c][p]
    __shared__ float b1s[CH];

    int t = threadIdx.x;
    int p0 = blockIdx.x * 16;

#pragma unroll
    for (int q = t; q < 1024; q += 256) {
        int o = q >> 4, c4 = (q & 15) * 4;
        float4 v = reinterpret_cast<const float4*>(w1)[q];
        W1T[c4 + 0][o] = v.x;
        W1T[c4 + 1][o] = v.y;
        W1T[c4 + 2][o] = v.z;
        W1T[c4 + 3][o] = v.w;
    }
    {
        int pl = t >> 4, c4 = (t & 15) * 4;
        float4 v = reinterpret_cast<const float4*>(x + p0 * CH)[t];
        xsT[c4 + 0][pl] = v.x;
        xsT[c4 + 1][pl] = v.y;
        xsT[c4 + 2][pl] = v.z;
        xsT[c4 + 3][pl] = v.w;
    }
    if (t < CH) b1s[t] = b1[t];
    __syncthreads();

    int o = t & 63, pg = t >> 6;
    float a0 = 0.f, a1 = 0.f, a2 = 0.f, a3 = 0.f;
#pragma unroll
    for (int c = 0; c < CH; ++c) {
        float wv = W1T[c][o];
        float4 xv = *reinterpret_cast<const float4*>(&xsT[c][pg * 4]);
        a0 += wv * xv.x;
        a1 += wv * xv.y;
        a2 += wv * xv.z;
        a3 += wv * xv.w;
    }

    float b1v = b1s[o];
    int pbase = p0 + pg * 4;
    g_Yj[(pbase + 0) * CH + o] = -a0;  g_Yi[(pbase + 0) * CH + o] = a0 + b1v;
    g_Yj[(pbase + 1) * CH + o] = -a1;  g_Yi[(pbase + 1) * CH + o] = a1 + b1v;
    g_Yj[(pbase + 2) * CH + o] = -a2;  g_Yi[(pbase + 2) * CH + o] = a2 + b1v;
    g_Yj[(pbase + 3) * CH + o] = -a3;  g_Yi[(pbase + 3) * CH + o] = a3 + b1v;
}

// ---------------------------------------------------------------------------
// K2: raw scores. score[i,j] = rI_i + rJn_j + sum_c w2h[c]*|Yi[i][c]+Yjn[j][c]|
// (Yjn pre-negated, so the pairwise sub is an add.)
// Block tile 64x64, 256 threads, 4x4 microtile. Grid: (jt=16, it=16, b=2)
// (Exact R3 configuration — proven at the fma issue floor.)
// ---------------------------------------------------------------------------
__global__ void k2_scores(const float* __restrict__ w2,
                          const float* __restrict__ b2p,
                          float* __restrict__ out) {
    __shared__ __align__(16) float Yis[64][68];
    __shared__ __align__(16) float Yjs[64][68];
    __shared__ float w2hs[CH];
    __shared__ float rIs[64], rJn[64];

    int t  = threadIdx.x;
    int jt = blockIdx.x, it = blockIdx.y, b = blockIdx.z;

    const float* Yi = g_Yi + ((b * NSEQ + it * 64) * CH);
    const float* Yj = g_Yj + ((b * NSEQ + jt * 64) * CH);

#pragma unroll
    for (int iter = 0; iter < 4; ++iter) {
        int q   = iter * 256 + t;
        int row = q >> 4, cq = (q & 15) * 4;
        float4 v = reinterpret_cast<const float4*>(Yi)[q];
        *reinterpret_cast<float4*>(&Yis[row][cq]) = v;
        float4 u = reinterpret_cast<const float4*>(Yj)[q];
        *reinterpret_cast<float4*>(&Yjs[row][cq]) = u;
    }
    if (t < CH) w2hs[t] = 0.5f * w2[t];
    __syncthreads();

    // Per-row scalars from staged tiles
    if (t < 64) {
        float a = 0.f;
#pragma unroll 8
        for (int c = 0; c < CH; ++c) a += w2hs[c] * Yis[t][c];
        rIs[t] = a + b2p[0];
    } else if (t < 128) {
        int j = t - 64;
        float a = 0.f;
#pragma unroll 8
        for (int c = 0; c < CH; ++c) a += w2hs[c] * Yjs[j][c];
        rJn[j] = a;  // Yjs holds -y, so this is already -rJ
    }
    __syncthreads();

    int tx = t & 15, ty = t >> 4;   // i_local = ty + 16r, j_local = tx + 16s
    float acc[4][4] = {};

#pragma unroll
    for (int c = 0; c < CH; c += 4) {
        float4 w4 = *reinterpret_cast<const float4*>(&w2hs[c]);
        float4 yi[4], yj[4];
#pragma unroll
        for (int r = 0; r < 4; ++r)
            yi[r] = *reinterpret_cast<const float4*>(&Yis[ty + 16 * r][c]);
#pragma unroll
        for (int s = 0; s < 4; ++s)
            yj[s] = *reinterpret_cast<const float4*>(&Yjs[tx + 16 * s][c]);
#pragma unroll
        for (int r = 0; r < 4; ++r)
#pragma unroll
            for (int s = 0; s < 4; ++s) {
                acc[r][s] += w4.x * fabsf(yi[r].x + yj[s].x);
                acc[r][s] += w4.y * fabsf(yi[r].y + yj[s].y);
                acc[r][s] += w4.z * fabsf(yi[r].z + yj[s].z);
                acc[r][s] += w4.w * fabsf(yi[r].w + yj[s].w);
            }
    }

#pragma unroll
    for (int r = 0; r < 4; ++r) {
        int ig   = it * 64 + ty + 16 * r;
        float ri = rIs[ty + 16 * r];
        float* orow = out + (size_t)(b * NSEQ + ig) * NSEQ + jt * 64;
#pragma unroll
        for (int s = 0; s < 4; ++s) {
            orow[tx + 16 * s] = ri + rJn[tx + 16 * s] + acc[r][s];
        }
    }
}

// ---------------------------------------------------------------------------
// K3: in-place row softmax over j. One block per (b,i) row. 256 threads,
// float4 vectorized (1 LDG.128 + 1 STG.128 per thread).
// ---------------------------------------------------------------------------
__global__ void k3_softmax(float* __restrict__ out) {
    __shared__ float red[8];
    __shared__ float bcast;
    size_t base = (size_t)blockIdx.x * NSEQ;
    int t = threadIdx.x;

    float4 v = reinterpret_cast<const float4*>(out + base)[t];

    float m = fmaxf(fmaxf(v.x, v.y), fmaxf(v.z, v.w));
#pragma unroll
    for (int o = 16; o; o >>= 1) m = fmaxf(m, __shfl_xor_sync(0xffffffffu, m, o));
    if ((t & 31) == 0) red[t >> 5] = m;
    __syncthreads();
    if (t == 0) {
        float mm = red[0];
#pragma unroll
        for (int i = 1; i < 8; ++i) mm = fmaxf(mm, red[i]);
        bcast = mm;
    }
    __syncthreads();
    m = bcast;

    float4 e;
    e.x = __expf(v.x - m);
    e.y = __expf(v.y - m);
    e.z = __expf(v.z - m);
    e.w = __expf(v.w - m);
    float s = (e.x + e.y) + (e.z + e.w);
#pragma unroll
    for (int o = 16; o; o >>= 1) s += __shfl_xor_sync(0xffffffffu, s, o);
    __syncthreads();
    if ((t & 31) == 0) red[t >> 5] = s;
    __syncthreads();
    if (t == 0) {
        float ss = red[0];
#pragma unroll
        for (int i = 1; i < 8; ++i) ss += red[i];
        bcast = 1.0f / ss;
    }
    __syncthreads();
    float inv = bcast;

    e.x *= inv;  e.y *= inv;  e.z *= inv;  e.w *= inv;
    reinterpret_cast<float4*>(out + base)[t] = e;
}

// ---------------------------------------------------------------------------
extern "C" void kernel_launch(void* const* d_in, const int* in_sizes, int n_in,
                              void* d_out, int out_size) {
    const float* x  = (const float*)d_in[0];  // [2,1024,64]
    const float* w1 = (const float*)d_in[1];  // [64,64]
    const float* b1 = (const float*)d_in[2];  // [64]
    const float* w2 = (const float*)d_in[3];  // [64]
    const float* b2 = (const float*)d_in[4];  // scalar
    float* out = (float*)d_out;               // [2,1024,1024]

    k1_proj<<<128, 256>>>(x, w1, b1);
    dim3 g2(16, 16, 2);
    k2_scores<<<g2, 256>>>(w2, b2, out);
    k3_softmax<<<2048, 256>>>(out);
}

// round 9
// speedup vs baseline: 1.8333x; 1.0846x over previous
#include <cuda_runtime.h>
#include <cuda_fp16.h>

#define NSEQ 1024
#define CH   64
#define NPTS (2 * NSEQ)

// Scratch (allocation-free rule: __device__ globals). fp16 projections.
__device__ __align__(16) __half g_Hi[NPTS * CH];  //  y + b1   (i side)
__device__ __align__(16) __half g_Hj[NPTS * CH];  // -y        (j side, pre-negated)

static __device__ __forceinline__ __half2 u2h(unsigned u) {
    return *reinterpret_cast<const __half2*>(&u);
}
static __device__ __forceinline__ unsigned h2u(__half2 h) {
    return *reinterpret_cast<const unsigned*>(&h);
}

// ---------------------------------------------------------------------------
// K1: y[p][o] = sum_c W1[o][c] * x[p][c];  Hi = half(y+b1); Hj = half(-y)
// 128 blocks x 16 points, 256 threads (proven fastest k1 shape).
// ---------------------------------------------------------------------------
__global__ void k1_proj(const float* __restrict__ x,
                        const float* __restrict__ w1,
                        const float* __restrict__ b1) {
    __shared__ float W1T[CH][65];                  // [c][o]
    __shared__ __align__(16) float xsT[CH][20];    // [c][p]
    __shared__ float b1s[CH];

    int t = threadIdx.x;
    int p0 = blockIdx.x * 16;

#pragma unroll
    for (int q = t; q < 1024; q += 256) {
        int o = q >> 4, c4 = (q & 15) * 4;
        float4 v = reinterpret_cast<const float4*>(w1)[q];
        W1T[c4 + 0][o] = v.x;
        W1T[c4 + 1][o] = v.y;
        W1T[c4 + 2][o] = v.z;
        W1T[c4 + 3][o] = v.w;
    }
    {
        int pl = t >> 4, c4 = (t & 15) * 4;
        float4 v = reinterpret_cast<const float4*>(x + p0 * CH)[t];
        xsT[c4 + 0][pl] = v.x;
        xsT[c4 + 1][pl] = v.y;
        xsT[c4 + 2][pl] = v.z;
        xsT[c4 + 3][pl] = v.w;
    }
    if (t < CH) b1s[t] = b1[t];
    __syncthreads();

    int o = t & 63, pg = t >> 6;
    float a0 = 0.f, a1 = 0.f, a2 = 0.f, a3 = 0.f;
#pragma unroll
    for (int c = 0; c < CH; ++c) {
        float wv = W1T[c][o];
        float4 xv = *reinterpret_cast<const float4*>(&xsT[c][pg * 4]);
        a0 += wv * xv.x;
        a1 += wv * xv.y;
        a2 += wv * xv.z;
        a3 += wv * xv.w;
    }

    float b1v = b1s[o];
    int pbase = p0 + pg * 4;
    g_Hj[(pbase + 0) * CH + o] = __float2half_rn(-a0);
    g_Hi[(pbase + 0) * CH + o] = __float2half_rn(a0 + b1v);
    g_Hj[(pbase + 1) * CH + o] = __float2half_rn(-a1);
    g_Hi[(pbase + 1) * CH + o] = __float2half_rn(a1 + b1v);
    g_Hj[(pbase + 2) * CH + o] = __float2half_rn(-a2);
    g_Hi[(pbase + 2) * CH + o] = __float2half_rn(a2 + b1v);
    g_Hj[(pbase + 3) * CH + o] = __float2half_rn(-a3);
    g_Hi[(pbase + 3) * CH + o] = __float2half_rn(a3 + b1v);
}

// ---------------------------------------------------------------------------
// K2: raw scores, fp16 packed pair math.
// score[i,j] = rI_i + rJn_j + sum_c w2h[c]*|Hi[i][c]+Hjn[j][c]|
// Tile 64x64 (=32 j-pairs), 256 threads, microtile 4i x 2jp (8 j) per thread.
// His: lane-duplicated half2 per (i,c); Hjs: (j,j+1)-paired half2 per (jp,c).
// fp16 accumulators dumped to fp32 every 16 channels.
// Grid: (jt=16, it=16, b=2)
// ---------------------------------------------------------------------------
__global__ void k2_scores(const float* __restrict__ w2,
                          const float* __restrict__ b2p,
                          float* __restrict__ out) {
    __shared__ __align__(16) unsigned His[64][66];   // dup'd (yi,yi)
    __shared__ __align__(16) unsigned Hjs[32][66];   // paired (yj0,yj1)
    __shared__ __align__(16) unsigned wdup[CH];      // dup'd (w2h,w2h)
    __shared__ float w2hs[CH];
    __shared__ float rIs[64], rJn[64];

    int t  = threadIdx.x;
    int jt = blockIdx.x, it = blockIdx.y, b = blockIdx.z;
    size_t bb = (size_t)b * NSEQ * CH;

    // --- stage His (dup): thread -> row t>>2, 16 channels ---
    {
        int row = t >> 2, c16 = (t & 3) * 16;
        const uint4* src = reinterpret_cast<const uint4*>(
            g_Hi + bb + (size_t)(it * 64 + row) * CH + c16);
        uint4 u0 = src[0], u1 = src[1];
        unsigned wsrc[8] = {u0.x, u0.y, u0.z, u0.w, u1.x, u1.y, u1.z, u1.w};
#pragma unroll
        for (int k = 0; k < 8; ++k) {
            His[row][c16 + 2 * k]     = __byte_perm(wsrc[k], 0, 0x1010);
            His[row][c16 + 2 * k + 1] = __byte_perm(wsrc[k], 0, 0x3232);
        }
    }
    // --- stage Hjs (j-pairs): thread -> jp = t>>3, 8 channels ---
    {
        int jp = t >> 3, c8 = (t & 7) * 8;
        const uint4* pa = reinterpret_cast<const uint4*>(
            g_Hj + bb + (size_t)(jt * 64 + 2 * jp) * CH + c8);
        const uint4* pb = reinterpret_cast<const uint4*>(
            g_Hj + bb + (size_t)(jt * 64 + 2 * jp + 1) * CH + c8);
        uint4 A = *pa, B = *pb;
        unsigned av[4] = {A.x, A.y, A.z, A.w};
        unsigned bv[4] = {B.x, B.y, B.z, B.w};
#pragma unroll
        for (int k = 0; k < 4; ++k) {
            Hjs[jp][c8 + 2 * k]     = __byte_perm(av[k], bv[k], 0x5410);
            Hjs[jp][c8 + 2 * k + 1] = __byte_perm(av[k], bv[k], 0x7632);
        }
    }
    if (t < CH) {
        float wh = 0.5f * w2[t];
        w2hs[t] = wh;
        wdup[t] = h2u(__half2half2(__float2half_rn(wh)));
    }
    __syncthreads();

    // --- per-row scalars (fp32 accumulate over fp16 values) ---
    if (t < 64) {
        const __half2* row = reinterpret_cast<const __half2*>(&His[t][0]);
        float a = 0.f;
#pragma unroll 8
        for (int c = 0; c < CH; ++c) a += w2hs[c] * __low2float(row[c]);
        rIs[t] = a + b2p[0];
    } else if (t < 128) {
        int j = t - 64, jp = j >> 1;
        const __half2* row = reinterpret_cast<const __half2*>(&Hjs[jp][0]);
        float a = 0.f;
        if (j & 1) {
#pragma unroll 8
            for (int c = 0; c < CH; ++c) a += w2hs[c] * __high2float(row[c]);
        } else {
#pragma unroll 8
            for (int c = 0; c < CH; ++c) a += w2hs[c] * __low2float(row[c]);
        }
        rJn[j] = a;
    }
    __syncthreads();

    int tx = t & 15, ty = t >> 4;   // i = ty+16r; jp = tx+16s (j = 2jp, 2jp+1)
    float accf[4][2][2] = {};

#pragma unroll
    for (int cd = 0; cd < 4; ++cd) {
        __half2 acc[4][2];
#pragma unroll
        for (int r = 0; r < 4; ++r)
#pragma unroll
            for (int s = 0; s < 2; ++s) acc[r][s] = __float2half2_rn(0.f);

#pragma unroll
        for (int c8 = 0; c8 < 8; ++c8) {
            int c = cd * 16 + c8 * 2;
            uint2 wv = *reinterpret_cast<const uint2*>(&wdup[c]);
            __half2 wA = u2h(wv.x), wB = u2h(wv.y);
            uint2 yi[4], zj[2];
#pragma unroll
            for (int r = 0; r < 4; ++r)
                yi[r] = *reinterpret_cast<const uint2*>(&His[ty + 16 * r][c]);
#pragma unroll
            for (int s = 0; s < 2; ++s)
                zj[s] = *reinterpret_cast<const uint2*>(&Hjs[tx + 16 * s][c]);
#pragma unroll
            for (int r = 0; r < 4; ++r)
#pragma unroll
                for (int s = 0; s < 2; ++s) {
                    __half2 dA = __habs2(__hadd2(u2h(yi[r].x), u2h(zj[s].x)));
                    acc[r][s] = __hfma2(wA, dA, acc[r][s]);
                    __half2 dB = __habs2(__hadd2(u2h(yi[r].y), u2h(zj[s].y)));
                    acc[r][s] = __hfma2(wB, dB, acc[r][s]);
                }
        }
#pragma unroll
        for (int r = 0; r < 4; ++r)
#pragma unroll
            for (int s = 0; s < 2; ++s) {
                float2 f = __half22float2(acc[r][s]);
                accf[r][s][0] += f.x;
                accf[r][s][1] += f.y;
            }
    }

#pragma unroll
    for (int r = 0; r < 4; ++r) {
        int il = ty + 16 * r;
        float ri = rIs[il];
        float* orow = out + ((size_t)(b * NSEQ + it * 64 + il)) * NSEQ + jt * 64;
#pragma unroll
        for (int s = 0; s < 2; ++s) {
            int j0 = 2 * (tx + 16 * s);
            float2 v;
            v.x = ri + rJn[j0]     + accf[r][s][0];
            v.y = ri + rJn[j0 + 1] + accf[r][s][1];
            *reinterpret_cast<float2*>(&orow[j0]) = v;
        }
    }
}

// ---------------------------------------------------------------------------
// K3: in-place row softmax over j. One block per (b,i) row. 256 threads,
// float4 vectorized.
// ---------------------------------------------------------------------------
__global__ void k3_softmax(float* __restrict__ out) {
    __shared__ float red[8];
    __shared__ float bcast;
    size_t base = (size_t)blockIdx.x * NSEQ;
    int t = threadIdx.x;

    float4 v = reinterpret_cast<const float4*>(out + base)[t];

    float m = fmaxf(fmaxf(v.x, v.y), fmaxf(v.z, v.w));
#pragma unroll
    for (int o = 16; o; o >>= 1) m = fmaxf(m, __shfl_xor_sync(0xffffffffu, m, o));
    if ((t & 31) == 0) red[t >> 5] = m;
    __syncthreads();
    if (t == 0) {
        float mm = red[0];
#pragma unroll
        for (int i = 1; i < 8; ++i) mm = fmaxf(mm, red[i]);
        bcast = mm;
    }
    __syncthreads();
    m = bcast;

    float4 e;
    e.x = __expf(v.x - m);
    e.y = __expf(v.y - m);
    e.z = __expf(v.z - m);
    e.w = __expf(v.w - m);
    float s = (e.x + e.y) + (e.z + e.w);
#pragma unroll
    for (int o = 16; o; o >>= 1) s += __shfl_xor_sync(0xffffffffu, s, o);
    __syncthreads();
    if ((t & 31) == 0) red[t >> 5] = s;
    __syncthreads();
    if (t == 0) {
        float ss = red[0];
#pragma unroll
        for (int i = 1; i < 8; ++i) ss += red[i];
        bcast = 1.0f / ss;
    }
    __syncthreads();
    float inv = bcast;

    e.x *= inv;  e.y *= inv;  e.z *= inv;  e.w *= inv;
    reinterpret_cast<float4*>(out + base)[t] = e;
}

// ---------------------------------------------------------------------------
extern "C" void kernel_launch(void* const* d_in, const int* in_sizes, int n_in,
                              void* d_out, int out_size) {
    const float* x  = (const float*)d_in[0];  // [2,1024,64]
    const float* w1 = (const float*)d_in[1];  // [64,64]
    const float* b1 = (const float*)d_in[2];  // [64]
    const float* w2 = (const float*)d_in[3];  // [64]
    const float* b2 = (const float*)d_in[4];  // scalar
    float* out = (float*)d_out;               // [2,1024,1024]

    k1_proj<<<128, 256>>>(x, w1, b1);
    dim3 g2(16, 16, 2);
    k2_scores<<<g2, 256>>>(w2, b2, out);
    k3_softmax<<<2048, 256>>>(out);
}